// round 13
// baseline (speedup 1.0000x reference)
#include <cuda_runtime.h>
#include <cuda_fp16.h>
#include <stdint.h>

// ============================================================
// Conv 3x3 pad=1 as fp16 implicit GEMM on HMMA, A-union tiling.
// R13: CTA 256x128 (512 thr, 16 warps of 64x32), 1 CTA/SM, 160 CTAs
// (5 overlapping m-tiles x 32 images, m0 = t*208). Register headroom
// (255 cap) + explicit frag double-buffering so LDSM overlaps HMMA.
// wait_group 0 pipeline (R8 semantics — proven correct).
// ============================================================

#define NPLANE 1156

__device__ __align__(256) __half g_xh[32 * NPLANE * 128];
__device__ __align__(256) __half g_wh[9 * 128 * 128];

__device__ __forceinline__ uint32_t smem_u32(const void* p) {
    uint32_t a;
    asm("{ .reg .u64 t; cvta.to.shared.u64 t, %1; cvt.u32.u64 %0, t; }" : "=r"(a) : "l"(p));
    return a;
}

#define CP_ASYNC16(dst, src, sz) \
    asm volatile("cp.async.cg.shared.global [%0], [%1], 16, %2;" :: "r"(dst), "l"(src), "r"(sz) : "memory")

__device__ __forceinline__ void ldm_x4(uint32_t* r, uint32_t addr) {
    asm volatile("ldmatrix.sync.aligned.m8n8.x4.shared.b16 {%0,%1,%2,%3}, [%4];"
                 : "=r"(r[0]), "=r"(r[1]), "=r"(r[2]), "=r"(r[3]) : "r"(addr));
}

__device__ __forceinline__ void mma_f16(float* c, const uint32_t* a, const uint32_t* b) {
    asm volatile(
        "mma.sync.aligned.m16n8k16.row.col.f32.f16.f16.f32 "
        "{%0,%1,%2,%3}, {%4,%5,%6,%7}, {%8,%9}, {%0,%1,%2,%3};"
        : "+f"(c[0]), "+f"(c[1]), "+f"(c[2]), "+f"(c[3])
        : "r"(a[0]), "r"(a[1]), "r"(a[2]), "r"(a[3]), "r"(b[0]), "r"(b[1]));
}

// ---------------- merged prep kernel ----------------

__global__ void prep_all(const float* __restrict__ x, const float* __restrict__ w) {
    const int bx = blockIdx.x, n = blockIdx.y, t = threadIdx.x;

    if (bx == 37) {
        #pragma unroll
        for (int r = 0; r < 2; ++r) {
            int id = n * 256 + t + r * 8192;
            int f = id >> 7, c = id & 127;
            const float* wp = w + (size_t)(f * 128 + c) * 9;
            #pragma unroll
            for (int q = 0; q < 9; ++q)
                g_wh[(q * 128 + f) * 128 + c] = __float2half(wp[q]);
        }
        return;
    }

    __shared__ float s[128][33];
    const int p0 = bx * 32;
    const int lane = t & 31, wrp = t >> 5;

    {
        int p = p0 + lane;
        int ph = p / 34, pw = p - ph * 34;
        int h = ph - 1, ww = pw - 1;
        bool ok = (p < NPLANE) && ((unsigned)h < 32u) && ((unsigned)ww < 32u);
        const float* xb = x + ((size_t)n * 128) * 1024 + h * 32 + ww;
        #pragma unroll
        for (int k = 0; k < 16; ++k) {
            int c = wrp * 16 + k;
            s[c][lane] = ok ? xb[(size_t)c * 1024] : 0.0f;
        }
    }
    __syncthreads();
    {
        int i = lane, cb = wrp * 16;
        int p = p0 + i;
        if (p < NPLANE) {
            __align__(16) __half hb[16];
            #pragma unroll
            for (int j = 0; j < 16; ++j) hb[j] = __float2half(s[cb + j][i]);
            size_t base = ((size_t)(n * NPLANE + p)) * 128 + cb;
            *(uint4*)(&g_xh[base])     = *(uint4*)(hb);
            *(uint4*)(&g_xh[base + 8]) = *(uint4*)(hb + 8);
        }
    }
}

// ---------------- main GEMM kernel ----------------
// 160 CTAs x 512 thr. T: n = T/5, mt = T%5, m0 = mt*208 (overlapping tiles).
// CTA tile 256m x 128f; 16 warps, 4Mx4N, warp tile 64x32.
// SMEM rows 144B: A-union 2 chunks x [326][144] @0; B ring 2 x [128][144].

#define ROWB 144
#define A_ROWS 326
#define A_STAGE 46944
#define B_BASE 93888
#define B_STAGE 18432
#define SMEM_DYN 130752
#define NUNITS 18
#define EPSTRIDE 18

__global__ __launch_bounds__(512, 1)
void conv_hmma(const float* __restrict__ bias, float* __restrict__ out) {
    extern __shared__ char dynsmem[];
    __shared__ float bias_s[128];

    const int tid = threadIdx.x, wid = tid >> 5, lane = tid & 31;
    const int wm = wid >> 2, wn = wid & 3;
    const int T = blockIdx.x;
    const int n = T / 5, m0 = (T % 5) * 208;

    if (tid < 128) bias_s[tid] = bias[tid];

    const uint32_t sd = smem_u32(dynsmem);

    auto load_A = [&](int chunk) {        // 326 rows x 8 x 16B = 2608 pieces
        const uint32_t abase = sd + chunk * A_STAGE;
        const int c0 = chunk * 64;
        #pragma unroll
        for (int it = 0; it < 6; ++it) {
            int idx = it * 512 + tid;
            if (idx < A_ROWS * 8) {
                int row = idx >> 3, ch = idx & 7;
                int p = m0 + row;
                int sz = 16;
                if (p >= NPLANE) { p = 0; sz = 0; }
                CP_ASYNC16(abase + row * ROWB + ch * 16,
                           g_xh + ((size_t)(n * NPLANE + p)) * 128 + c0 + ch * 8, sz);
            }
        }
    };

    auto load_B = [&](int u) {
        const int q = u % 9, chunk = u / 9, c0 = chunk * 64;
        const uint32_t bbase = sd + B_BASE + (u & 1) * B_STAGE;
        #pragma unroll
        for (int it = 0; it < 2; ++it) {
            int idx = it * 512 + tid;
            int row = idx >> 3, ch = idx & 7;
            CP_ASYNC16(bbase + row * ROWB + ch * 16,
                       g_wh + (size_t)((q * 128 + row) * 128) + c0 + ch * 8, 16);
        }
    };

    float acc[4][4][4];
    #pragma unroll
    for (int i = 0; i < 4; ++i)
        #pragma unroll
        for (int j = 0; j < 4; ++j)
            #pragma unroll
            for (int r = 0; r < 4; ++r) acc[i][j][r] = 0.0f;

    const uint32_t a_lrow = (uint32_t)(wm * 64 + (lane & 15)) * ROWB + ((lane >> 4) << 4);
    const uint32_t b_lrow = (uint32_t)(wn * 32 + ((lane >> 4) << 3) + (lane & 7)) * ROWB
                            + ((lane & 8) ? 16u : 0u);

    // prologue: G1 = {B0, A0}, G2 = {B1, A1}
    load_B(0);
    load_A(0);
    asm volatile("cp.async.commit_group;" ::: "memory");
    load_B(1);
    load_A(1);
    asm volatile("cp.async.commit_group;" ::: "memory");

    for (int u = 0; u < NUNITS; ++u) {
        asm volatile("cp.async.wait_group 0;" ::: "memory");
        __syncthreads();                  // all loads visible; warps past u-1
        if (u + 1 < NUNITS) {             // prefetch B(u+1), overlaps compute(u)
            load_B(u + 1);
            asm volatile("cp.async.commit_group;" ::: "memory");
        }

        const int q = u % 9, chunk = u / 9;
        const int shift = (q / 3) * 34 + (q % 3);
        const uint32_t abase = sd + chunk * A_STAGE + (uint32_t)shift * ROWB + a_lrow;
        const uint32_t bbase = sd + B_BASE + (u & 1) * B_STAGE + b_lrow;

        // double-buffered fragments: load frags(k+1) before MMAs(k)
        uint32_t Af[2][16], Bf[2][8];
        {
            #pragma unroll
            for (int i = 0; i < 4; ++i) ldm_x4(&Af[0][4 * i], abase + i * 16 * ROWB);
            ldm_x4(&Bf[0][0], bbase);
            ldm_x4(&Bf[0][4], bbase + 16 * ROWB);
        }
        #pragma unroll
        for (int ks = 0; ks < 4; ++ks) {
            const int cur = ks & 1, nxt = cur ^ 1;
            if (ks + 1 < 4) {
                const uint32_t ao = abase + (ks + 1) * 32;
                #pragma unroll
                for (int i = 0; i < 4; ++i) ldm_x4(&Af[nxt][4 * i], ao + i * 16 * ROWB);
                const uint32_t bo = bbase + (ks + 1) * 32;
                ldm_x4(&Bf[nxt][0], bo);
                ldm_x4(&Bf[nxt][4], bo + 16 * ROWB);
            }
            #pragma unroll
            for (int i = 0; i < 4; ++i)
                #pragma unroll
                for (int j = 0; j < 4; ++j)
                    mma_f16(acc[i][j], &Af[cur][4 * i], &Bf[cur][(j >> 1) * 4 + (j & 1) * 2]);
        }
    }

    __syncthreads();

    // ---------------- epilogue: 2 f-chunks of 16 via smem ----------------
    float* eps = (float*)dynsmem + wid * (64 * EPSTRIDE);  // 4608B/warp x16 = 73728
    const int g = lane >> 2, tg = lane & 3;
    const int mwbase = m0 + wm * 64;
    float* outn = out + (size_t)n * 128 * 1024;

    #pragma unroll
    for (int cj = 0; cj < 2; ++cj) {
        __syncwarp();
        #pragma unroll
        for (int i = 0; i < 4; ++i)
            #pragma unroll
            for (int jj = 0; jj < 2; ++jj) {
                int j = cj * 2 + jj;
                float* p0 = &eps[(i * 16 + g) * EPSTRIDE + jj * 8 + 2 * tg];
                float* p1 = &eps[(i * 16 + g + 8) * EPSTRIDE + jj * 8 + 2 * tg];
                *(float2*)p0 = make_float2(acc[i][j][0], acc[i][j][1]);
                *(float2*)p1 = make_float2(acc[i][j][2], acc[i][j][3]);
            }
        __syncwarp();

        #pragma unroll 1
        for (int f = 0; f < 16; ++f) {
            const int fg = wn * 32 + cj * 16 + f;
            const float bv = bias_s[fg];
            #pragma unroll
            for (int half = 0; half < 2; ++half) {
                int ml = half * 32 + lane;
                int m = mwbase + ml;
                int hh = m / 34, ww = m % 34;
                if (hh < 32 && ww < 32)
                    outn[(size_t)fg * 1024 + hh * 32 + ww] = eps[ml * EPSTRIDE + f] + bv;
            }
        }
    }
}

// ---------------- launch ----------------

extern "C" void kernel_launch(void* const* d_in, const int* in_sizes, int n_in,
                              void* d_out, int out_size) {
    const float* x = (const float*)d_in[0];
    const float* w = (const float*)d_in[1];
    const float* b = (const float*)d_in[2];
    float* out = (float*)d_out;

    cudaFuncSetAttribute(conv_hmma, cudaFuncAttributeMaxDynamicSharedMemorySize, SMEM_DYN);

    dim3 gp(38, 32);
    prep_all<<<gp, 256>>>(x, w);
    conv_hmma<<<160, 512, SMEM_DYN>>>(b, out);
}

// round 14
// speedup vs baseline: 1.6250x; 1.6250x over previous
#include <cuda_runtime.h>
#include <cuda_fp16.h>
#include <stdint.h>

// ============================================================
// Conv 3x3 pad=1 as fp16 implicit GEMM on HMMA, A-union tiling.
// R14: 256-thr CTAs (reg cap 128 at 2 CTA/SM), CTA tile 64m x 128f,
// 8 warps of 32x32. Per unit: B frags for ALL 4 k-steps preloaded
// (32 regs), A frags double-buffered (16 regs) -> LDSM(A,k+1)
// overlaps MMA(k). 576 CTAs = 32 n x 18 m-tiles (64 rows each).
// ============================================================

#define NPLANE 1156

__device__ __align__(256) __half g_xh[32 * NPLANE * 128];
__device__ __align__(256) __half g_wh[9 * 128 * 128];

__device__ __forceinline__ uint32_t smem_u32(const void* p) {
    uint32_t a;
    asm("{ .reg .u64 t; cvta.to.shared.u64 t, %1; cvt.u32.u64 %0, t; }" : "=r"(a) : "l"(p));
    return a;
}

#define CP_ASYNC16(dst, src, sz) \
    asm volatile("cp.async.cg.shared.global [%0], [%1], 16, %2;" :: "r"(dst), "l"(src), "r"(sz) : "memory")

__device__ __forceinline__ void ldm_x4(uint32_t* r, uint32_t addr) {
    asm volatile("ldmatrix.sync.aligned.m8n8.x4.shared.b16 {%0,%1,%2,%3}, [%4];"
                 : "=r"(r[0]), "=r"(r[1]), "=r"(r[2]), "=r"(r[3]) : "r"(addr));
}

__device__ __forceinline__ void mma_f16(float* c, const uint32_t* a, const uint32_t* b) {
    asm volatile(
        "mma.sync.aligned.m16n8k16.row.col.f32.f16.f16.f32 "
        "{%0,%1,%2,%3}, {%4,%5,%6,%7}, {%8,%9}, {%0,%1,%2,%3};"
        : "+f"(c[0]), "+f"(c[1]), "+f"(c[2]), "+f"(c[3])
        : "r"(a[0]), "r"(a[1]), "r"(a[2]), "r"(a[3]), "r"(b[0]), "r"(b[1]));
}

// ---------------- merged prep kernel ----------------

__global__ void prep_all(const float* __restrict__ x, const float* __restrict__ w) {
    const int bx = blockIdx.x, n = blockIdx.y, t = threadIdx.x;

    if (bx == 37) {
        #pragma unroll
        for (int r = 0; r < 2; ++r) {
            int id = n * 256 + t + r * 8192;
            int f = id >> 7, c = id & 127;
            const float* wp = w + (size_t)(f * 128 + c) * 9;
            #pragma unroll
            for (int q = 0; q < 9; ++q)
                g_wh[(q * 128 + f) * 128 + c] = __float2half(wp[q]);
        }
        return;
    }

    __shared__ float s[128][33];
    const int p0 = bx * 32;
    const int lane = t & 31, wrp = t >> 5;

    {
        int p = p0 + lane;
        int ph = p / 34, pw = p - ph * 34;
        int h = ph - 1, ww = pw - 1;
        bool ok = (p < NPLANE) && ((unsigned)h < 32u) && ((unsigned)ww < 32u);
        const float* xb = x + ((size_t)n * 128) * 1024 + h * 32 + ww;
        #pragma unroll
        for (int k = 0; k < 16; ++k) {
            int c = wrp * 16 + k;
            s[c][lane] = ok ? xb[(size_t)c * 1024] : 0.0f;
        }
    }
    __syncthreads();
    {
        int i = lane, cb = wrp * 16;
        int p = p0 + i;
        if (p < NPLANE) {
            __align__(16) __half hb[16];
            #pragma unroll
            for (int j = 0; j < 16; ++j) hb[j] = __float2half(s[cb + j][i]);
            size_t base = ((size_t)(n * NPLANE + p)) * 128 + cb;
            *(uint4*)(&g_xh[base])     = *(uint4*)(hb);
            *(uint4*)(&g_xh[base + 8]) = *(uint4*)(hb + 8);
        }
    }
}

// ---------------- main GEMM kernel ----------------
// 576 CTAs x 256 thr: T -> n = T/18, mt = T%18, m0 = mt*64.
// CTA tile 64m x 128f; 8 warps, 2Mx4N grid, warp tile 32x32.
// SMEM rows 144B: A-union 2 chunks x [134][144] @0; B ring 2 x [128][144].

#define ROWB 144
#define A_ROWS 134
#define A_STAGE 19296
#define B_BASE 38592
#define B_STAGE 18432
#define SMEM_DYN 75456
#define NUNITS 18
#define EPSTRIDE 18

__global__ __launch_bounds__(256, 2)
void conv_hmma(const float* __restrict__ bias, float* __restrict__ out) {
    extern __shared__ char dynsmem[];
    __shared__ float bias_s[128];

    const int tid = threadIdx.x, wid = tid >> 5, lane = tid & 31;
    const int wm = wid >> 2, wn = wid & 3;
    const int T = blockIdx.x;
    const int n = T / 18, m0 = (T % 18) * 64;

    if (tid < 128) bias_s[tid] = bias[tid];

    const uint32_t sd = smem_u32(dynsmem);

    auto load_A = [&](int chunk) {        // 134 rows x 8 x 16B = 1072 pieces
        const uint32_t abase = sd + chunk * A_STAGE;
        const int c0 = chunk * 64;
        #pragma unroll
        for (int it = 0; it < 5; ++it) {
            int idx = it * 256 + tid;
            if (idx < A_ROWS * 8) {
                int row = idx >> 3, ch = idx & 7;
                int p = m0 + row;
                int sz = 16;
                if (p >= NPLANE) { p = 0; sz = 0; }
                CP_ASYNC16(abase + row * ROWB + ch * 16,
                           g_xh + ((size_t)(n * NPLANE + p)) * 128 + c0 + ch * 8, sz);
            }
        }
    };

    auto load_B = [&](int u) {            // 128 rows x 8 x 16B = 1024 pieces
        const int q = u % 9, chunk = u / 9, c0 = chunk * 64;
        const uint32_t bbase = sd + B_BASE + (u & 1) * B_STAGE;
        #pragma unroll
        for (int it = 0; it < 4; ++it) {
            int idx = it * 256 + tid;
            int row = idx >> 3, ch = idx & 7;
            CP_ASYNC16(bbase + row * ROWB + ch * 16,
                       g_wh + (size_t)((q * 128 + row) * 128) + c0 + ch * 8, 16);
        }
    };

    float acc[2][4][4];
    #pragma unroll
    for (int i = 0; i < 2; ++i)
        #pragma unroll
        for (int j = 0; j < 4; ++j)
            #pragma unroll
            for (int r = 0; r < 4; ++r) acc[i][j][r] = 0.0f;

    const uint32_t a_lrow = (uint32_t)(wm * 32 + (lane & 15)) * ROWB + ((lane >> 4) << 4);
    const uint32_t b_lrow = (uint32_t)(wn * 32 + ((lane >> 4) << 3) + (lane & 7)) * ROWB
                            + ((lane & 8) ? 16u : 0u);

    // prologue: G1 = {B0, A0}, G2 = {B1, A1}
    load_B(0);
    load_A(0);
    asm volatile("cp.async.commit_group;" ::: "memory");
    load_B(1);
    load_A(1);
    asm volatile("cp.async.commit_group;" ::: "memory");

    for (int u = 0; u < NUNITS; ++u) {
        asm volatile("cp.async.wait_group 0;" ::: "memory");
        __syncthreads();                  // loads visible; all warps past u-1
        if (u + 1 < NUNITS) {             // prefetch B(u+1), lands before unit u+1
            load_B(u + 1);
            asm volatile("cp.async.commit_group;" ::: "memory");
        }

        const int q = u % 9, chunk = u / 9;
        const int shift = (q / 3) * 34 + (q % 3);
        const uint32_t abase = sd + chunk * A_STAGE + (uint32_t)shift * ROWB + a_lrow;
        const uint32_t bbase = sd + B_BASE + (u & 1) * B_STAGE + b_lrow;

        // preload B for ALL 4 k-steps (32 regs), double-buffer A (16 regs)
        uint32_t Bf[4][8];
        #pragma unroll
        for (int ks = 0; ks < 4; ++ks) {
            ldm_x4(&Bf[ks][0], bbase + ks * 32);
            ldm_x4(&Bf[ks][4], bbase + ks * 32 + 16 * ROWB);
        }
        uint32_t Af[2][8];
        ldm_x4(&Af[0][0], abase);
        ldm_x4(&Af[0][4], abase + 16 * ROWB);

        #pragma unroll
        for (int ks = 0; ks < 4; ++ks) {
            const int cur = ks & 1, nxt = cur ^ 1;
            if (ks < 3) {                 // independent of MMA(ks) -> overlaps
                const uint32_t ao = abase + (ks + 1) * 32;
                ldm_x4(&Af[nxt][0], ao);
                ldm_x4(&Af[nxt][4], ao + 16 * ROWB);
            }
            #pragma unroll
            for (int i = 0; i < 2; ++i)
                #pragma unroll
                for (int j = 0; j < 4; ++j)
                    mma_f16(acc[i][j], &Af[cur][4 * i], &Bf[ks][(j >> 1) * 4 + (j & 1) * 2]);
        }
    }

    __syncthreads();

    // ---------------- epilogue: 2 f-chunks of 16 via smem ----------------
    float* eps = (float*)dynsmem + wid * (32 * EPSTRIDE);  // 2304B/warp x8 = 18432
    const int g = lane >> 2, tg = lane & 3;
    const int mwbase = m0 + wm * 32;
    float* outn = out + (size_t)n * 128 * 1024;

    #pragma unroll
    for (int cj = 0; cj < 2; ++cj) {
        __syncwarp();
        #pragma unroll
        for (int i = 0; i < 2; ++i)
            #pragma unroll
            for (int jj = 0; jj < 2; ++jj) {
                int j = cj * 2 + jj;
                float* p0 = &eps[(i * 16 + g) * EPSTRIDE + jj * 8 + 2 * tg];
                float* p1 = &eps[(i * 16 + g + 8) * EPSTRIDE + jj * 8 + 2 * tg];
                *(float2*)p0 = make_float2(acc[i][j][0], acc[i][j][1]);
                *(float2*)p1 = make_float2(acc[i][j][2], acc[i][j][3]);
            }
        __syncwarp();

        #pragma unroll 1
        for (int f = 0; f < 16; ++f) {
            const int fg = wn * 32 + cj * 16 + f;
            const float bv = bias_s[fg];
            int m = mwbase + lane;
            int hh = m / 34, ww = m % 34;
            if (hh < 32 && ww < 32)
                outn[(size_t)fg * 1024 + hh * 32 + ww] = eps[lane * EPSTRIDE + f] + bv;
        }
    }
}

// ---------------- launch ----------------

extern "C" void kernel_launch(void* const* d_in, const int* in_sizes, int n_in,
                              void* d_out, int out_size) {
    const float* x = (const float*)d_in[0];
    const float* w = (const float*)d_in[1];
    const float* b = (const float*)d_in[2];
    float* out = (float*)d_out;

    cudaFuncSetAttribute(conv_hmma, cudaFuncAttributeMaxDynamicSharedMemorySize, SMEM_DYN);

    dim3 gp(38, 32);
    prep_all<<<gp, 256>>>(x, w);
    conv_hmma<<<576, 256, SMEM_DYN>>>(b, out);
}

// round 15
// speedup vs baseline: 1.7161x; 1.0560x over previous
#include <cuda_runtime.h>
#include <cuda_fp16.h>
#include <stdint.h>

// ============================================================
// Conv 3x3 pad=1 as fp16 implicit GEMM on HMMA, A-union tiling.
// R15 = R8 (best: 34.2us main / 41.5 total) + warp-staggered k-step
// order: ks = (ksi + wid) & 3. Breaks the barrier-induced phase lock
// where all warps LDSM-burst then MMA-burst together (LDS and tensor
// pipes serialized 17.2us + 17.8us). Order-only change, zero risk.
// ============================================================

#define NPLANE 1156

__device__ __align__(256) __half g_xh[32 * NPLANE * 128];
__device__ __align__(256) __half g_wh[9 * 128 * 128];

__device__ __forceinline__ uint32_t smem_u32(const void* p) {
    uint32_t a;
    asm("{ .reg .u64 t; cvta.to.shared.u64 t, %1; cvt.u32.u64 %0, t; }" : "=r"(a) : "l"(p));
    return a;
}

#define CP_ASYNC16(dst, src, sz) \
    asm volatile("cp.async.cg.shared.global [%0], [%1], 16, %2;" :: "r"(dst), "l"(src), "r"(sz) : "memory")

__device__ __forceinline__ void ldm_x4(uint32_t* r, uint32_t addr) {
    asm volatile("ldmatrix.sync.aligned.m8n8.x4.shared.b16 {%0,%1,%2,%3}, [%4];"
                 : "=r"(r[0]), "=r"(r[1]), "=r"(r[2]), "=r"(r[3]) : "r"(addr));
}

__device__ __forceinline__ void mma_f16(float* c, const uint32_t* a, const uint32_t* b) {
    asm volatile(
        "mma.sync.aligned.m16n8k16.row.col.f32.f16.f16.f32 "
        "{%0,%1,%2,%3}, {%4,%5,%6,%7}, {%8,%9}, {%0,%1,%2,%3};"
        : "+f"(c[0]), "+f"(c[1]), "+f"(c[2]), "+f"(c[3])
        : "r"(a[0]), "r"(a[1]), "r"(a[2]), "r"(a[3]), "r"(b[0]), "r"(b[1]));
}

// ---------------- merged prep kernel ----------------

__global__ void prep_all(const float* __restrict__ x, const float* __restrict__ w) {
    const int bx = blockIdx.x, n = blockIdx.y, t = threadIdx.x;

    if (bx == 37) {
        #pragma unroll
        for (int r = 0; r < 2; ++r) {
            int id = n * 256 + t + r * 8192;
            int f = id >> 7, c = id & 127;
            const float* wp = w + (size_t)(f * 128 + c) * 9;
            #pragma unroll
            for (int q = 0; q < 9; ++q)
                g_wh[(q * 128 + f) * 128 + c] = __float2half(wp[q]);
        }
        return;
    }

    __shared__ float s[128][33];
    const int p0 = bx * 32;
    const int lane = t & 31, wrp = t >> 5;

    {
        int p = p0 + lane;
        int ph = p / 34, pw = p - ph * 34;
        int h = ph - 1, ww = pw - 1;
        bool ok = (p < NPLANE) && ((unsigned)h < 32u) && ((unsigned)ww < 32u);
        const float* xb = x + ((size_t)n * 128) * 1024 + h * 32 + ww;
        #pragma unroll
        for (int k = 0; k < 16; ++k) {
            int c = wrp * 16 + k;
            s[c][lane] = ok ? xb[(size_t)c * 1024] : 0.0f;
        }
    }
    __syncthreads();
    {
        int i = lane, cb = wrp * 16;
        int p = p0 + i;
        if (p < NPLANE) {
            __align__(16) __half hb[16];
            #pragma unroll
            for (int j = 0; j < 16; ++j) hb[j] = __float2half(s[cb + j][i]);
            size_t base = ((size_t)(n * NPLANE + p)) * 128 + cb;
            *(uint4*)(&g_xh[base])     = *(uint4*)(hb);
            *(uint4*)(&g_xh[base + 8]) = *(uint4*)(hb + 8);
        }
    }
}

// ---------------- main GEMM kernel ----------------
// 288 CTAs x 512 thr (16 warps, grid 4Mx4N, warp tile 32x32).
// SMEM rows 144B: A-union 2 x [204][144] @0; B ring 2 x [128][144] @58752.

#define ROWB 144
#define A_STAGE 29376
#define B_BASE 58752
#define B_STAGE 18432
#define SMEM_DYN 95616
#define NUNITS 18
#define EPSTRIDE 18

__global__ __launch_bounds__(512, 2)
void conv_hmma(const float* __restrict__ bias, float* __restrict__ out) {
    extern __shared__ char dynsmem[];
    __shared__ float bias_s[128];

    const int tid = threadIdx.x, wid = tid >> 5, lane = tid & 31;
    const int wm = wid >> 2, wn = wid & 3;
    const int T = blockIdx.x;
    const int n = T / 9, m0 = (T % 9) * 128;

    if (tid < 128) bias_s[tid] = bias[tid];

    const uint32_t sd = smem_u32(dynsmem);

    auto load_A = [&](int chunk) {
        const uint32_t abase = sd + chunk * A_STAGE;
        const int c0 = chunk * 64;
        #pragma unroll
        for (int it = 0; it < 4; ++it) {
            int idx = it * 512 + tid;
            if (idx < 1632) {
                int row = idx >> 3, ch = idx & 7;
                int p = m0 + row;
                int sz = 16;
                if (p >= NPLANE) { p = 0; sz = 0; }
                CP_ASYNC16(abase + row * ROWB + ch * 16,
                           g_xh + ((size_t)(n * NPLANE + p)) * 128 + c0 + ch * 8, sz);
            }
        }
        asm volatile("cp.async.commit_group;" ::: "memory");
    };

    auto load_B = [&](int u) {
        const int q = u % 9, chunk = u / 9, c0 = chunk * 64;
        const uint32_t bbase = sd + B_BASE + (u & 1) * B_STAGE;
        #pragma unroll
        for (int it = 0; it < 2; ++it) {
            int idx = it * 512 + tid;
            int row = idx >> 3, ch = idx & 7;
            CP_ASYNC16(bbase + row * ROWB + ch * 16,
                       g_wh + (size_t)((q * 128 + row) * 128) + c0 + ch * 8, 16);
        }
        asm volatile("cp.async.commit_group;" ::: "memory");
    };

    float acc[2][4][4];
    #pragma unroll
    for (int i = 0; i < 2; ++i)
        #pragma unroll
        for (int j = 0; j < 4; ++j)
            #pragma unroll
            for (int r = 0; r < 4; ++r) acc[i][j][r] = 0.0f;

    const uint32_t a_lrow = (uint32_t)(wm * 32 + (lane & 15)) * ROWB + ((lane >> 4) << 4);
    const uint32_t b_lrow = (uint32_t)(wn * 32 + ((lane >> 4) << 3) + (lane & 7)) * ROWB
                            + ((lane & 8) ? 16u : 0u);

    load_A(0);
    load_A(1);
    load_B(0);
    load_B(1);

    // per-warp k-step rotation: decorrelates LDSM/MMA phases across warps
    const int krot = wid & 3;

    for (int u = 0; u < NUNITS; ++u) {
        asm volatile("cp.async.wait_group 0;" ::: "memory");
        __syncthreads();
        if (u + 1 < NUNITS) load_B(u + 1);

        const int q = u % 9, chunk = u / 9;
        const int shift = (q / 3) * 34 + (q % 3);
        const uint32_t abase = sd + chunk * A_STAGE + (uint32_t)shift * ROWB + a_lrow;
        const uint32_t bbase = sd + B_BASE + (u & 1) * B_STAGE + b_lrow;

        #pragma unroll
        for (int ksi = 0; ksi < 4; ++ksi) {
            const int ks = (ksi + krot) & 3;   // staggered order per warp
            uint32_t Ah[8], Bh[8];
            const uint32_t ao = abase + ks * 32;
            ldm_x4(&Ah[0], ao);
            ldm_x4(&Ah[4], ao + 16 * ROWB);
            const uint32_t bo = bbase + ks * 32;
            ldm_x4(&Bh[0], bo);
            ldm_x4(&Bh[4], bo + 16 * ROWB);

            #pragma unroll
            for (int i = 0; i < 2; ++i)
                #pragma unroll
                for (int j = 0; j < 4; ++j)
                    mma_f16(acc[i][j], &Ah[4 * i], &Bh[(j >> 1) * 4 + (j & 1) * 2]);
        }
    }

    __syncthreads();

    // ---------------- epilogue: 2 f-chunks of 16 via smem ----------------
    float* eps = (float*)dynsmem + wid * (32 * EPSTRIDE);
    const int g = lane >> 2, tg = lane & 3;
    const int mwbase = m0 + wm * 32;
    float* outn = out + (size_t)n * 128 * 1024;

    #pragma unroll
    for (int cj = 0; cj < 2; ++cj) {
        __syncwarp();
        #pragma unroll
        for (int i = 0; i < 2; ++i)
            #pragma unroll
            for (int jj = 0; jj < 2; ++jj) {
                int j = cj * 2 + jj;
                float* p0 = &eps[(i * 16 + g) * EPSTRIDE + jj * 8 + 2 * tg];
                float* p1 = &eps[(i * 16 + g + 8) * EPSTRIDE + jj * 8 + 2 * tg];
                *(float2*)p0 = make_float2(acc[i][j][0], acc[i][j][1]);
                *(float2*)p1 = make_float2(acc[i][j][2], acc[i][j][3]);
            }
        __syncwarp();

        #pragma unroll 1
        for (int f = 0; f < 16; ++f) {
            const int fg = wn * 32 + cj * 16 + f;
            const float bv = bias_s[fg];
            int m = mwbase + lane;
            int hh = m / 34, ww = m % 34;
            if (hh < 32 && ww < 32)
                outn[(size_t)fg * 1024 + hh * 32 + ww] = eps[lane * EPSTRIDE + f] + bv;
        }
    }
}

// ---------------- launch ----------------

extern "C" void kernel_launch(void* const* d_in, const int* in_sizes, int n_in,
                              void* d_out, int out_size) {
    const float* x = (const float*)d_in[0];
    const float* w = (const float*)d_in[1];
    const float* b = (const float*)d_in[2];
    float* out = (float*)d_out;

    cudaFuncSetAttribute(conv_hmma, cudaFuncAttributeMaxDynamicSharedMemorySize, SMEM_DYN);

    dim3 gp(38, 32);
    prep_all<<<gp, 256>>>(x, w);
    conv_hmma<<<288, 512, SMEM_DYN>>>(b, out);
}